// round 3
// baseline (speedup 1.0000x reference)
#include <cuda_runtime.h>
#include <stdint.h>

#define BM 128
#define BN 128
#define BK 16

// 32768 x 3072 fp32 intermediate (gelu(fc1)) — static device scratch (no allocs).
static __device__ float g_H[(size_t)32768 * 3072];

__device__ __forceinline__ unsigned long long pack2(float x, float y) {
    unsigned long long r;
    asm("mov.b64 %0, {%1, %2};" : "=l"(r) : "f"(x), "f"(y));
    return r;
}
__device__ __forceinline__ void unpack2(unsigned long long v, float& x, float& y) {
    asm("mov.b64 {%0, %1}, %2;" : "=f"(x), "=f"(y) : "l"(v));
}
__device__ __forceinline__ float gelu_exact(float x) {
    // torch 'gelu' (exact): 0.5*x*(1+erf(x/sqrt(2)))
    return 0.5f * x * (1.0f + erff(x * 0.7071067811865475244f));
}

// ---------------------------------------------------------------------------
// GEMM1: C = gelu(A[32768,768] @ B[768,3072] + bias), C -> g_H
// 128x128 tile, 256 threads, 8x8 per thread, f32x2 packed FMAs.
// ---------------------------------------------------------------------------
__global__ void __launch_bounds__(256, 2)
k_gemm1(const float* __restrict__ A, const float* __restrict__ B,
        const float* __restrict__ bias)
{
    const int N = 3072, K = 768;
    __shared__ __align__(16) float As[BK][BM + 4];   // +4 pad: conflict-mitigated transposed stores, 16B-aligned rows
    __shared__ __align__(16) float Bs[BK][BN];

    const int tid = threadIdx.x;
    const int bx = blockIdx.x, by = blockIdx.y;
    const int rowBase = (tid >> 4) << 3;   // (tid/16)*8
    const int colBase = (tid & 15) << 3;   // (tid%16)*8

    const float* Ablk = A + (size_t)by * BM * K;
    const float* Bblk = B + (size_t)bx * BN;

    unsigned long long acc[8][4];
    #pragma unroll
    for (int i = 0; i < 8; i++)
        #pragma unroll
        for (int j = 0; j < 4; j++) acc[i][j] = 0ull;

    for (int k0 = 0; k0 < K; k0 += BK) {
        // Load A tile [BM x BK], store transposed As[k][m]
        #pragma unroll
        for (int t = 0; t < 2; t++) {
            int idx = tid + t * 256;
            int ar = idx >> 2;            // 0..127
            int ac = (idx & 3) << 2;      // 0,4,8,12
            float4 v = *(const float4*)(Ablk + (size_t)ar * K + k0 + ac);
            As[ac + 0][ar] = v.x;
            As[ac + 1][ar] = v.y;
            As[ac + 2][ar] = v.z;
            As[ac + 3][ar] = v.w;
        }
        // Load B tile [BK x BN] straight
        #pragma unroll
        for (int t = 0; t < 2; t++) {
            int idx = tid + t * 256;
            int br = idx >> 5;            // 0..15
            int bc = (idx & 31) << 2;     // 0..124
            *(float4*)(&Bs[br][bc]) =
                *(const float4*)(Bblk + (size_t)(k0 + br) * N + bc);
        }
        __syncthreads();

        #pragma unroll
        for (int k = 0; k < BK; k++) {
            float4 a0 = *(const float4*)(&As[k][rowBase]);
            float4 a1 = *(const float4*)(&As[k][rowBase + 4]);
            const unsigned long long* bp =
                (const unsigned long long*)(&Bs[k][colBase]);
            unsigned long long bv0 = bp[0], bv1 = bp[1], bv2 = bp[2], bv3 = bp[3];
            float av[8] = {a0.x, a0.y, a0.z, a0.w, a1.x, a1.y, a1.z, a1.w};
            #pragma unroll
            for (int i = 0; i < 8; i++) {
                unsigned long long a2 = pack2(av[i], av[i]);
                asm("fma.rn.f32x2 %0, %1, %2, %0;" : "+l"(acc[i][0]) : "l"(a2), "l"(bv0));
                asm("fma.rn.f32x2 %0, %1, %2, %0;" : "+l"(acc[i][1]) : "l"(a2), "l"(bv1));
                asm("fma.rn.f32x2 %0, %1, %2, %0;" : "+l"(acc[i][2]) : "l"(a2), "l"(bv2));
                asm("fma.rn.f32x2 %0, %1, %2, %0;" : "+l"(acc[i][3]) : "l"(a2), "l"(bv3));
            }
        }
        __syncthreads();
    }

    // Epilogue: bias + exact GELU, write to g_H
    const int colg = bx * BN + colBase;
    float bv[8];
    #pragma unroll
    for (int j = 0; j < 8; j++) bv[j] = bias[colg + j];

    #pragma unroll
    for (int i = 0; i < 8; i++) {
        size_t row = (size_t)by * BM + rowBase + i;
        float o[8];
        #pragma unroll
        for (int j2 = 0; j2 < 4; j2++) {
            float x, y;
            unpack2(acc[i][j2], x, y);
            o[2 * j2]     = gelu_exact(x + bv[2 * j2]);
            o[2 * j2 + 1] = gelu_exact(y + bv[2 * j2 + 1]);
        }
        float4* dst = (float4*)(g_H + row * N + colg);
        dst[0] = make_float4(o[0], o[1], o[2], o[3]);
        dst[1] = make_float4(o[4], o[5], o[6], o[7]);
    }
}

// Robust index load: reference declares int64 but jax w/o x64 emits int32.
// If the buffer is int64, every odd 32-bit word is 0 (values in [0,6)).
__device__ __forceinline__ int load_expert_index(const int* __restrict__ idx32, int b) {
    int odd_or = 0;
    #pragma unroll
    for (int j = 1; j < 32; j += 2) odd_or |= idx32[j];
    return (odd_or == 0) ? idx32[2 * b] : idx32[b];
}

// ---------------------------------------------------------------------------
// GEMM2: out = g_H[32768,3072] @ [W2 | We[idx[b]]] + [b2 | be[idx[b]]]
// N = 768 (576 shared + 192 expert). 128-row tiles stay within one batch.
// ---------------------------------------------------------------------------
__global__ void __launch_bounds__(256, 2)
k_gemm2(const float* __restrict__ W2, const float* __restrict__ b2,
        const float* __restrict__ We, const float* __restrict__ be,
        const int* __restrict__ idx32, float* __restrict__ C)
{
    const int N = 768, K = 3072;
    __shared__ __align__(16) float As[BK][BM + 4];
    __shared__ __align__(16) float Bs[BK][BN];

    const int tid = threadIdx.x;
    const int bx = blockIdx.x, by = blockIdx.y;
    const int rowBase = (tid >> 4) << 3;
    const int colBase = (tid & 15) << 3;

    const int e = load_expert_index(idx32, by >> 3);   // 1024 rows / 128 = 8 blocks per batch
    const float* Wexp = We + (size_t)e * (3072 * 192);
    const float* Ablk = g_H + (size_t)by * BM * K;

    unsigned long long acc[8][4];
    #pragma unroll
    for (int i = 0; i < 8; i++)
        #pragma unroll
        for (int j = 0; j < 4; j++) acc[i][j] = 0ull;

    for (int k0 = 0; k0 < K; k0 += BK) {
        #pragma unroll
        for (int t = 0; t < 2; t++) {
            int idx = tid + t * 256;
            int ar = idx >> 2;
            int ac = (idx & 3) << 2;
            float4 v = *(const float4*)(Ablk + (size_t)ar * K + k0 + ac);
            As[ac + 0][ar] = v.x;
            As[ac + 1][ar] = v.y;
            As[ac + 2][ar] = v.z;
            As[ac + 3][ar] = v.w;
        }
        // B tile: columns [0,576) from W2, [576,768) from the routed expert.
        // col is a multiple of 4 and 576 % 4 == 0 -> each float4 is homogeneous.
        #pragma unroll
        for (int t = 0; t < 2; t++) {
            int idx = tid + t * 256;
            int br = idx >> 5;
            int bc = (idx & 31) << 2;
            int col = bx * BN + bc;
            int kk = k0 + br;
            float4 v = (col < 576)
                ? *(const float4*)(W2 + (size_t)kk * 576 + col)
                : *(const float4*)(Wexp + (size_t)kk * 192 + (col - 576));
            *(float4*)(&Bs[br][bc]) = v;
        }
        __syncthreads();

        #pragma unroll
        for (int k = 0; k < BK; k++) {
            float4 a0 = *(const float4*)(&As[k][rowBase]);
            float4 a1 = *(const float4*)(&As[k][rowBase + 4]);
            const unsigned long long* bp =
                (const unsigned long long*)(&Bs[k][colBase]);
            unsigned long long bv0 = bp[0], bv1 = bp[1], bv2 = bp[2], bv3 = bp[3];
            float av[8] = {a0.x, a0.y, a0.z, a0.w, a1.x, a1.y, a1.z, a1.w};
            #pragma unroll
            for (int i = 0; i < 8; i++) {
                unsigned long long a2 = pack2(av[i], av[i]);
                asm("fma.rn.f32x2 %0, %1, %2, %0;" : "+l"(acc[i][0]) : "l"(a2), "l"(bv0));
                asm("fma.rn.f32x2 %0, %1, %2, %0;" : "+l"(acc[i][1]) : "l"(a2), "l"(bv1));
                asm("fma.rn.f32x2 %0, %1, %2, %0;" : "+l"(acc[i][2]) : "l"(a2), "l"(bv2));
                asm("fma.rn.f32x2 %0, %1, %2, %0;" : "+l"(acc[i][3]) : "l"(a2), "l"(bv3));
            }
        }
        __syncthreads();
    }

    // Epilogue: bias (shared or expert), plain add, write out
    const int colg = bx * BN + colBase;
    float bv[8];
    #pragma unroll
    for (int j = 0; j < 8; j++) {
        int c = colg + j;
        bv[j] = (c < 576) ? b2[c] : be[e * 192 + (c - 576)];
    }

    #pragma unroll
    for (int i = 0; i < 8; i++) {
        size_t row = (size_t)by * BM + rowBase + i;
        float o[8];
        #pragma unroll
        for (int j2 = 0; j2 < 4; j2++) {
            float x, y;
            unpack2(acc[i][j2], x, y);
            o[2 * j2]     = x + bv[2 * j2];
            o[2 * j2 + 1] = y + bv[2 * j2 + 1];
        }
        float4* dst = (float4*)(C + row * N + colg);
        dst[0] = make_float4(o[0], o[1], o[2], o[3]);
        dst[1] = make_float4(o[4], o[5], o[6], o[7]);
    }
}

extern "C" void kernel_launch(void* const* d_in, const int* in_sizes, int n_in,
                              void* d_out, int out_size)
{
    (void)in_sizes; (void)n_in; (void)out_size;
    const float* X   = (const float*)d_in[0];
    const int*   idx = (const int*)d_in[1];    // int64-or-int32 detected on device
    const float* W1  = (const float*)d_in[2];
    const float* b1  = (const float*)d_in[3];
    const float* W2  = (const float*)d_in[4];
    const float* b2  = (const float*)d_in[5];
    const float* We  = (const float*)d_in[6];
    const float* be  = (const float*)d_in[7];
    float* out = (float*)d_out;

    dim3 g1(3072 / BN, 32768 / BM);   // 24 x 256
    k_gemm1<<<g1, 256>>>(X, W1, b1);

    dim3 g2(768 / BN, 32768 / BM);    // 6 x 256
    k_gemm2<<<g2, 256>>>(W2, b2, We, be, idx, out);
}

// round 6
// speedup vs baseline: 1.4862x; 1.4862x over previous
#include <cuda_runtime.h>
#include <cuda_bf16.h>
#include <stdint.h>

// ---------------------------------------------------------------------------
// bf16 split-2 (3-product) emulated-fp32 GEMMs on the legacy mma.sync path
// (tcgen05 is unavailable: harness compiles at virtual target compute_103).
// CTA tile 128x128, Kc=32, 3-stage cp.async pipeline, warp tile 32x64.
// ---------------------------------------------------------------------------

#define STAGE_BYTES 32768          // Ahi 8K | Alo 8K | Bhi 8K | Blo 8K
#define NSTAGES 3
#define SMEM_TOTAL (NSTAGES * STAGE_BYTES)

// ---------------- static device scratch (no allocations allowed) -----------
static __device__ __align__(16) __nv_bfloat16 g_Xhi[(size_t)32768 * 768];
static __device__ __align__(16) __nv_bfloat16 g_Xlo[(size_t)32768 * 768];
static __device__ __align__(16) __nv_bfloat16 g_W1hi[(size_t)3072 * 768];   // [N][K]
static __device__ __align__(16) __nv_bfloat16 g_W1lo[(size_t)3072 * 768];
static __device__ __align__(16) __nv_bfloat16 g_W2hi[(size_t)576 * 3072];   // [N][K]
static __device__ __align__(16) __nv_bfloat16 g_W2lo[(size_t)576 * 3072];
static __device__ __align__(16) __nv_bfloat16 g_Wehi[(size_t)6 * 192 * 3072];
static __device__ __align__(16) __nv_bfloat16 g_Welo[(size_t)6 * 192 * 3072];
static __device__ __align__(16) __nv_bfloat16 g_Hhi[(size_t)32768 * 3072];
static __device__ __align__(16) __nv_bfloat16 g_Hlo[(size_t)32768 * 3072];

// ---------------- PTX helpers ----------------------------------------------
__device__ __forceinline__ uint32_t smem_u32(const void* p) {
    uint32_t a;
    asm("{ .reg .u64 t; cvta.to.shared.u64 t, %1; cvt.u32.u64 %0, t; }" : "=r"(a) : "l"(p));
    return a;
}
__device__ __forceinline__ void cp16(uint32_t saddr, const void* g) {
    asm volatile("cp.async.cg.shared.global [%0], [%1], 16;" :: "r"(saddr), "l"(g));
}
#define CP_COMMIT() asm volatile("cp.async.commit_group;" ::: "memory")
#define CP_WAIT(n)  asm volatile("cp.async.wait_group " #n ";" ::: "memory")

__device__ __forceinline__ void ldsm4(uint32_t* r, uint32_t addr) {
    asm volatile("ldmatrix.sync.aligned.m8n8.x4.shared.b16 {%0,%1,%2,%3}, [%4];"
        : "=r"(r[0]), "=r"(r[1]), "=r"(r[2]), "=r"(r[3]) : "r"(addr));
}
__device__ __forceinline__ void mma_bf16(float* c, const uint32_t* a, const uint32_t* b) {
    asm volatile("mma.sync.aligned.m16n8k16.row.col.f32.bf16.bf16.f32 "
        "{%0,%1,%2,%3}, {%4,%5,%6,%7}, {%8,%9}, {%0,%1,%2,%3};"
        : "+f"(c[0]), "+f"(c[1]), "+f"(c[2]), "+f"(c[3])
        : "r"(a[0]), "r"(a[1]), "r"(a[2]), "r"(a[3]), "r"(b[0]), "r"(b[1]));
}

__device__ __forceinline__ float gelu_exact(float x) {
    return 0.5f * x * (1.0f + erff(x * 0.7071067811865475244f));
}
__device__ __forceinline__ uint32_t pack_bf2(float a, float b) {
    __nv_bfloat162 t = __floats2bfloat162_rn(a, b);
    return *reinterpret_cast<uint32_t*>(&t);
}
// int64-vs-int32 robust expert index (values in [0,6) -> int64 odd words all 0)
__device__ __forceinline__ int load_expert_index(const int* __restrict__ idx32, int b) {
    int odd_or = 0;
    #pragma unroll
    for (int j = 1; j < 32; j += 2) odd_or |= idx32[j];
    return (odd_or == 0) ? idx32[2 * b] : idx32[b];
}

// ---------------- prep: fp32 -> (hi, lo) bf16 split -------------------------
__global__ void k_split(const float* __restrict__ s, __nv_bfloat16* __restrict__ hi,
                        __nv_bfloat16* __restrict__ lo, size_t n)
{
    size_t i = ((size_t)blockIdx.x * blockDim.x + threadIdx.x) * 4;
    if (i >= n) return;
    float4 v = *(const float4*)(s + i);
    uint32_t h0 = pack_bf2(v.x, v.y), h1 = pack_bf2(v.z, v.w);
    __nv_bfloat162 hh0 = *reinterpret_cast<__nv_bfloat162*>(&h0);
    __nv_bfloat162 hh1 = *reinterpret_cast<__nv_bfloat162*>(&h1);
    uint32_t l0 = pack_bf2(v.x - __bfloat162float(__low2bfloat16(hh0)),
                           v.y - __bfloat162float(__high2bfloat16(hh0)));
    uint32_t l1 = pack_bf2(v.z - __bfloat162float(__low2bfloat16(hh1)),
                           v.w - __bfloat162float(__high2bfloat16(hh1)));
    *(uint2*)(hi + i) = make_uint2(h0, h1);
    *(uint2*)(lo + i) = make_uint2(l0, l1);
}

// prep: transpose [R][C] fp32 -> [C][R] bf16 hi/lo (batched over z)
__global__ void k_tsplit(const float* __restrict__ src, __nv_bfloat16* __restrict__ dhi,
                         __nv_bfloat16* __restrict__ dlo, int R, int C)
{
    __shared__ float t[32][33];
    size_t zo = (size_t)blockIdx.z * R * C;
    int bx = blockIdx.x * 32, by = blockIdx.y * 32;
    int tx = threadIdx.x, ty = threadIdx.y;  // (32, 8)
    #pragma unroll
    for (int i = 0; i < 32; i += 8)
        t[ty + i][tx] = src[zo + (size_t)(by + ty + i) * C + bx + tx];
    __syncthreads();
    #pragma unroll
    for (int i = 0; i < 32; i += 8) {
        float v = t[tx][ty + i];
        __nv_bfloat16 h = __float2bfloat16_rn(v);
        float l = v - __bfloat162float(h);
        size_t o = zo + (size_t)(bx + ty + i) * R + (by + tx);
        dhi[o] = h;
        dlo[o] = __float2bfloat16_rn(l);
    }
}

// ---------------------------------------------------------------------------
// Shared mainloop machinery (macro-free inline): per chunk c, stage buffers at
// st = (c % 3) * 32768; halves: Ahi +0, Alo +8192, Bhi +16384, Blo +24576.
// SMEM row = 64 B (32 bf16); 16B chunk swizzle p = c ^ ((r>>1)&3).
// ---------------------------------------------------------------------------

struct Frags {
    float acc[2][8][4];
};

__device__ __forceinline__ void compute_chunk(uint32_t base, int st, int lane,
                                              int wm, int wn, Frags& F)
{
    const uint32_t Ab = base + st;
    const uint32_t Bb = base + st + 16384;
    const int m8 = lane >> 3, l7 = lane & 7;
    #pragma unroll
    for (int ks = 0; ks < 2; ks++) {
        uint32_t ah[2][4], al[2][4], bh[8][2], bl[8][2];
        #pragma unroll
        for (int mi = 0; mi < 2; mi++) {
            int rr = wm * 32 + mi * 16 + (m8 & 1) * 8 + l7;
            int ch = ks * 2 + (m8 >> 1);
            int p = ch ^ ((rr >> 1) & 3);
            uint32_t off = (uint32_t)(rr * 64 + p * 16);
            ldsm4(ah[mi], Ab + off);
            ldsm4(al[mi], Ab + 8192 + off);
        }
        #pragma unroll
        for (int jp = 0; jp < 4; jp++) {
            int nrow = wn * 64 + jp * 16 + (m8 >> 1) * 8 + l7;
            int ch = ks * 2 + (m8 & 1);
            int p = ch ^ ((nrow >> 1) & 3);
            uint32_t off = (uint32_t)(nrow * 64 + p * 16);
            uint32_t tmp[4];
            ldsm4(tmp, Bb + off);
            bh[2 * jp][0] = tmp[0]; bh[2 * jp][1] = tmp[1];
            bh[2 * jp + 1][0] = tmp[2]; bh[2 * jp + 1][1] = tmp[3];
            ldsm4(tmp, Bb + 8192 + off);
            bl[2 * jp][0] = tmp[0]; bl[2 * jp][1] = tmp[1];
            bl[2 * jp + 1][0] = tmp[2]; bl[2 * jp + 1][1] = tmp[3];
        }
        #pragma unroll
        for (int mi = 0; mi < 2; mi++)
            #pragma unroll
            for (int nj = 0; nj < 8; nj++) {
                mma_bf16(F.acc[mi][nj], ah[mi], bh[nj]);
                mma_bf16(F.acc[mi][nj], ah[mi], bl[nj]);
                mma_bf16(F.acc[mi][nj], al[mi], bh[nj]);
            }
    }
}

// ---------------------------------------------------------------------------
// GEMM1: H = gelu(X @ W1 + b1).  A = X hi/lo [32768][768], B = W1t [3072][768]
// Grid (24, 256), 256 threads.
// ---------------------------------------------------------------------------
__global__ void __launch_bounds__(256, 1)
k_mm1(const float* __restrict__ b1)
{
    extern __shared__ char smem[];
    const uint32_t base = smem_u32(smem);
    const int tid = threadIdx.x, wid = tid >> 5, lane = tid & 31;
    const int bx = blockIdx.x, by = blockIdx.y;
    const int K = 768, NC = 24;
    const int wm = wid & 3, wn = wid >> 2;

    auto issue = [&](int c) {
        int st = (c % NSTAGES) * STAGE_BYTES;
        #pragma unroll
        for (int t = 0; t < 8; t++) {
            int idx = tid + t * 256;
            int half = idx >> 9, w = idx & 511, r = w >> 2, ch = w & 3;
            int p = ch ^ ((r >> 1) & 3);
            uint32_t sa = base + st + half * 8192 + r * 64 + p * 16;
            const __nv_bfloat16* src;
            size_t grow;
            if (half < 2) { src = half ? g_Xlo : g_Xhi;  grow = (size_t)(by * 128 + r) * K; }
            else          { src = (half == 3) ? g_W1lo : g_W1hi; grow = (size_t)(bx * 128 + r) * K; }
            cp16(sa, src + grow + c * 32 + ch * 8);
        }
        CP_COMMIT();
    };

    Frags F;
    #pragma unroll
    for (int mi = 0; mi < 2; mi++)
        #pragma unroll
        for (int nj = 0; nj < 8; nj++)
            #pragma unroll
            for (int q = 0; q < 4; q++) F.acc[mi][nj][q] = 0.0f;

    issue(0);
    issue(1);
    for (int c = 0; c < NC; c++) {
        if (c + 2 < NC) { issue(c + 2); CP_WAIT(2); }
        else if (c + 1 < NC) { CP_WAIT(1); }
        else { CP_WAIT(0); }
        __syncthreads();
        compute_chunk(base, (c % NSTAGES) * STAGE_BYTES, lane, wm, wn, F);
        __syncthreads();
    }

    // epilogue: bias + exact GELU -> split hi/lo bf16 into H
    const int g = lane >> 2, t4 = lane & 3;
    #pragma unroll
    for (int mi = 0; mi < 2; mi++) {
        #pragma unroll
        for (int nj = 0; nj < 8; nj++) {
            int row0 = by * 128 + wm * 32 + mi * 16 + g;
            int col  = bx * 128 + wn * 64 + nj * 8 + 2 * t4;
            float2 bb = *(const float2*)(b1 + col);
            float x0 = gelu_exact(F.acc[mi][nj][0] + bb.x);
            float x1 = gelu_exact(F.acc[mi][nj][1] + bb.y);
            float x2 = gelu_exact(F.acc[mi][nj][2] + bb.x);
            float x3 = gelu_exact(F.acc[mi][nj][3] + bb.y);
            uint32_t h01 = pack_bf2(x0, x1), h23 = pack_bf2(x2, x3);
            __nv_bfloat162 hb01 = *reinterpret_cast<__nv_bfloat162*>(&h01);
            __nv_bfloat162 hb23 = *reinterpret_cast<__nv_bfloat162*>(&h23);
            uint32_t l01 = pack_bf2(x0 - __bfloat162float(__low2bfloat16(hb01)),
                                    x1 - __bfloat162float(__high2bfloat16(hb01)));
            uint32_t l23 = pack_bf2(x2 - __bfloat162float(__low2bfloat16(hb23)),
                                    x3 - __bfloat162float(__high2bfloat16(hb23)));
            *(uint32_t*)(g_Hhi + (size_t)row0 * 3072 + col) = h01;
            *(uint32_t*)(g_Hlo + (size_t)row0 * 3072 + col) = l01;
            *(uint32_t*)(g_Hhi + (size_t)(row0 + 8) * 3072 + col) = h23;
            *(uint32_t*)(g_Hlo + (size_t)(row0 + 8) * 3072 + col) = l23;
        }
    }
}

// ---------------------------------------------------------------------------
// GEMM2: out = H @ [W2 | We[idx]] + [b2 | be[idx]].  Grid (6, 256).
// B rows n<576 from W2t, n>=576 from Wet[e]; 128-row M tiles never straddle
// a batch (1024 rows / batch).
// ---------------------------------------------------------------------------
__global__ void __launch_bounds__(256, 1)
k_mm2(const float* __restrict__ b2, const float* __restrict__ be,
      const int* __restrict__ idx32, float* __restrict__ out)
{
    extern __shared__ char smem[];
    const uint32_t base = smem_u32(smem);
    const int tid = threadIdx.x, wid = tid >> 5, lane = tid & 31;
    const int bx = blockIdx.x, by = blockIdx.y;
    const int K = 3072, NC = 96;
    const int wm = wid & 3, wn = wid >> 2;
    const int e = load_expert_index(idx32, by >> 3);

    auto issue = [&](int c) {
        int st = (c % NSTAGES) * STAGE_BYTES;
        #pragma unroll
        for (int t = 0; t < 8; t++) {
            int idx = tid + t * 256;
            int half = idx >> 9, w = idx & 511, r = w >> 2, ch = w & 3;
            int p = ch ^ ((r >> 1) & 3);
            uint32_t sa = base + st + half * 8192 + r * 64 + p * 16;
            const __nv_bfloat16* src;
            size_t grow;
            if (half < 2) {
                src = half ? g_Hlo : g_Hhi;
                grow = (size_t)(by * 128 + r) * K;
            } else {
                int n = bx * 128 + r;
                if (n < 576) { src = (half == 3) ? g_W2lo : g_W2hi; grow = (size_t)n * K; }
                else { src = (half == 3) ? g_Welo : g_Wehi;
                       grow = ((size_t)e * 192 + (n - 576)) * K; }
            }
            cp16(sa, src + grow + c * 32 + ch * 8);
        }
        CP_COMMIT();
    };

    Frags F;
    #pragma unroll
    for (int mi = 0; mi < 2; mi++)
        #pragma unroll
        for (int nj = 0; nj < 8; nj++)
            #pragma unroll
            for (int q = 0; q < 4; q++) F.acc[mi][nj][q] = 0.0f;

    issue(0);
    issue(1);
    for (int c = 0; c < NC; c++) {
        if (c + 2 < NC) { issue(c + 2); CP_WAIT(2); }
        else if (c + 1 < NC) { CP_WAIT(1); }
        else { CP_WAIT(0); }
        __syncthreads();
        compute_chunk(base, (c % NSTAGES) * STAGE_BYTES, lane, wm, wn, F);
        __syncthreads();
    }

    // epilogue: + bias (shared / expert), fp32 out [32768][768]
    const int g = lane >> 2, t4 = lane & 3;
    #pragma unroll
    for (int mi = 0; mi < 2; mi++) {
        #pragma unroll
        for (int nj = 0; nj < 8; nj++) {
            int row0 = by * 128 + wm * 32 + mi * 16 + g;
            int col  = bx * 128 + wn * 64 + nj * 8 + 2 * t4;
            float bx0, bx1;
            if (col < 576) { float2 bb = *(const float2*)(b2 + col); bx0 = bb.x; bx1 = bb.y; }
            else { float2 bb = *(const float2*)(be + e * 192 + (col - 576)); bx0 = bb.x; bx1 = bb.y; }
            float2 v0 = make_float2(F.acc[mi][nj][0] + bx0, F.acc[mi][nj][1] + bx1);
            float2 v1 = make_float2(F.acc[mi][nj][2] + bx0, F.acc[mi][nj][3] + bx1);
            *(float2*)(out + (size_t)row0 * 768 + col) = v0;
            *(float2*)(out + (size_t)(row0 + 8) * 768 + col) = v1;
        }
    }
}

// ---------------------------------------------------------------------------
extern "C" void kernel_launch(void* const* d_in, const int* in_sizes, int n_in,
                              void* d_out, int out_size)
{
    (void)in_sizes; (void)n_in; (void)out_size;
    const float* X   = (const float*)d_in[0];
    const int*   idx = (const int*)d_in[1];
    const float* W1  = (const float*)d_in[2];
    const float* b1  = (const float*)d_in[3];
    const float* W2  = (const float*)d_in[4];
    const float* b2  = (const float*)d_in[5];
    const float* We  = (const float*)d_in[6];
    const float* be  = (const float*)d_in[7];
    float* out = (float*)d_out;

    cudaFuncSetAttribute(k_mm1, cudaFuncAttributeMaxDynamicSharedMemorySize, SMEM_TOTAL);
    cudaFuncSetAttribute(k_mm2, cudaFuncAttributeMaxDynamicSharedMemorySize, SMEM_TOTAL);

    __nv_bfloat16 *xhi, *xlo, *w1hi, *w1lo, *w2hi, *w2lo, *wehi, *welo;
    cudaGetSymbolAddress((void**)&xhi,  g_Xhi);
    cudaGetSymbolAddress((void**)&xlo,  g_Xlo);
    cudaGetSymbolAddress((void**)&w1hi, g_W1hi);
    cudaGetSymbolAddress((void**)&w1lo, g_W1lo);
    cudaGetSymbolAddress((void**)&w2hi, g_W2hi);
    cudaGetSymbolAddress((void**)&w2lo, g_W2lo);
    cudaGetSymbolAddress((void**)&wehi, g_Wehi);
    cudaGetSymbolAddress((void**)&welo, g_Welo);

    {
        size_t n = (size_t)32768 * 768;
        k_split<<<(unsigned)(n / (256 * 4)), 256>>>(X, xhi, xlo, n);
    }
    {
        dim3 b(32, 8);
        k_tsplit<<<dim3(3072 / 32, 768 / 32, 1), b>>>(W1, w1hi, w1lo, 768, 3072);
        k_tsplit<<<dim3(576 / 32, 3072 / 32, 1), b>>>(W2, w2hi, w2lo, 3072, 576);
        k_tsplit<<<dim3(192 / 32, 3072 / 32, 6), b>>>(We, wehi, welo, 3072, 192);
    }

    k_mm1<<<dim3(3072 / 128, 32768 / 128), 256, SMEM_TOTAL>>>(b1);
    k_mm2<<<dim3(768 / 128, 32768 / 128), 256, SMEM_TOTAL>>>(b2, be, idx, out);
}

// round 7
// speedup vs baseline: 2.8539x; 1.9203x over previous
#include <cuda_runtime.h>
#include <cuda_bf16.h>
#include <stdint.h>

// ---------------------------------------------------------------------------
// bf16 split-2 (3-product) emulated-fp32 GEMMs on the legacy mma.sync path
// (tcgen05 unavailable: harness compiles at virtual target compute_103).
// CTA tile 128x128, Kc=32, 3-stage cp.async pipeline, warp tile 32x64.
// R7: 2 CTAs/SM co-residency (192KB smem/SM), register-disciplined mainloop.
// ---------------------------------------------------------------------------

#define STAGE_BYTES 32768          // Ahi 8K | Alo 8K | Bhi 8K | Blo 8K
#define NSTAGES 3
#define SMEM_TOTAL (NSTAGES * STAGE_BYTES)

// ---------------- static device scratch (no allocations allowed) -----------
static __device__ __align__(16) __nv_bfloat16 g_Xhi[(size_t)32768 * 768];
static __device__ __align__(16) __nv_bfloat16 g_Xlo[(size_t)32768 * 768];
static __device__ __align__(16) __nv_bfloat16 g_W1hi[(size_t)3072 * 768];   // [N][K]
static __device__ __align__(16) __nv_bfloat16 g_W1lo[(size_t)3072 * 768];
static __device__ __align__(16) __nv_bfloat16 g_W2hi[(size_t)576 * 3072];   // [N][K]
static __device__ __align__(16) __nv_bfloat16 g_W2lo[(size_t)576 * 3072];
static __device__ __align__(16) __nv_bfloat16 g_Wehi[(size_t)6 * 192 * 3072];
static __device__ __align__(16) __nv_bfloat16 g_Welo[(size_t)6 * 192 * 3072];
static __device__ __align__(16) __nv_bfloat16 g_Hhi[(size_t)32768 * 3072];
static __device__ __align__(16) __nv_bfloat16 g_Hlo[(size_t)32768 * 3072];

// ---------------- PTX helpers ----------------------------------------------
__device__ __forceinline__ uint32_t smem_u32(const void* p) {
    uint32_t a;
    asm("{ .reg .u64 t; cvta.to.shared.u64 t, %1; cvt.u32.u64 %0, t; }" : "=r"(a) : "l"(p));
    return a;
}
__device__ __forceinline__ void cp16(uint32_t saddr, const void* g) {
    asm volatile("cp.async.cg.shared.global [%0], [%1], 16;" :: "r"(saddr), "l"(g));
}
#define CP_COMMIT() asm volatile("cp.async.commit_group;" ::: "memory")
#define CP_WAIT(n)  asm volatile("cp.async.wait_group " #n ";" ::: "memory")

__device__ __forceinline__ void ldsm4(uint32_t* r, uint32_t addr) {
    asm volatile("ldmatrix.sync.aligned.m8n8.x4.shared.b16 {%0,%1,%2,%3}, [%4];"
        : "=r"(r[0]), "=r"(r[1]), "=r"(r[2]), "=r"(r[3]) : "r"(addr));
}
__device__ __forceinline__ void mma_bf16(float* c, const uint32_t* a,
                                         uint32_t b0, uint32_t b1) {
    asm volatile("mma.sync.aligned.m16n8k16.row.col.f32.bf16.bf16.f32 "
        "{%0,%1,%2,%3}, {%4,%5,%6,%7}, {%8,%9}, {%0,%1,%2,%3};"
        : "+f"(c[0]), "+f"(c[1]), "+f"(c[2]), "+f"(c[3])
        : "r"(a[0]), "r"(a[1]), "r"(a[2]), "r"(a[3]), "r"(b0), "r"(b1));
}

__device__ __forceinline__ float gelu_exact(float x) {
    return 0.5f * x * (1.0f + erff(x * 0.7071067811865475244f));
}
__device__ __forceinline__ uint32_t pack_bf2(float a, float b) {
    __nv_bfloat162 t = __floats2bfloat162_rn(a, b);
    return *reinterpret_cast<uint32_t*>(&t);
}
// int64-vs-int32 robust expert index (values in [0,6) -> int64 odd words all 0)
__device__ __forceinline__ int load_expert_index(const int* __restrict__ idx32, int b) {
    int odd_or = 0;
    #pragma unroll
    for (int j = 1; j < 32; j += 2) odd_or |= idx32[j];
    return (odd_or == 0) ? idx32[2 * b] : idx32[b];
}

// ---------------- prep: fp32 -> (hi, lo) bf16 split -------------------------
__global__ void k_split(const float* __restrict__ s, __nv_bfloat16* __restrict__ hi,
                        __nv_bfloat16* __restrict__ lo, size_t n)
{
    size_t i = ((size_t)blockIdx.x * blockDim.x + threadIdx.x) * 4;
    if (i >= n) return;
    float4 v = *(const float4*)(s + i);
    uint32_t h0 = pack_bf2(v.x, v.y), h1 = pack_bf2(v.z, v.w);
    __nv_bfloat162 hh0 = *reinterpret_cast<__nv_bfloat162*>(&h0);
    __nv_bfloat162 hh1 = *reinterpret_cast<__nv_bfloat162*>(&h1);
    uint32_t l0 = pack_bf2(v.x - __bfloat162float(__low2bfloat16(hh0)),
                           v.y - __bfloat162float(__high2bfloat16(hh0)));
    uint32_t l1 = pack_bf2(v.z - __bfloat162float(__low2bfloat16(hh1)),
                           v.w - __bfloat162float(__high2bfloat16(hh1)));
    *(uint2*)(hi + i) = make_uint2(h0, h1);
    *(uint2*)(lo + i) = make_uint2(l0, l1);
}

// prep: transpose [R][C] fp32 -> [C][R] bf16 hi/lo (batched over z)
__global__ void k_tsplit(const float* __restrict__ src, __nv_bfloat16* __restrict__ dhi,
                         __nv_bfloat16* __restrict__ dlo, int R, int C)
{
    __shared__ float t[32][33];
    size_t zo = (size_t)blockIdx.z * R * C;
    int bx = blockIdx.x * 32, by = blockIdx.y * 32;
    int tx = threadIdx.x, ty = threadIdx.y;  // (32, 8)
    #pragma unroll
    for (int i = 0; i < 32; i += 8)
        t[ty + i][tx] = src[zo + (size_t)(by + ty + i) * C + bx + tx];
    __syncthreads();
    #pragma unroll
    for (int i = 0; i < 32; i += 8) {
        float v = t[tx][ty + i];
        __nv_bfloat16 h = __float2bfloat16_rn(v);
        float l = v - __bfloat162float(h);
        size_t o = zo + (size_t)(bx + ty + i) * R + (by + tx);
        dhi[o] = h;
        dlo[o] = __float2bfloat16_rn(l);
    }
}

// ---------------------------------------------------------------------------
// Mainloop compute: per chunk c, stage buffers at st = (c % 3) * 32768;
// halves: Ahi +0, Alo +8192, Bhi +16384, Blo +24576.
// SMEM row = 64 B (32 bf16); 16B chunk swizzle p = c ^ ((r>>1)&3).
// Register-lean: A hi/lo frags hoisted per k-step; B frags per-jp, consumed
// immediately (live regs ~ 64 acc + 16 A + 8 B + addr).
// ---------------------------------------------------------------------------

struct Frags {
    float acc[2][8][4];
};

__device__ __forceinline__ void compute_chunk(uint32_t base, int st, int lane,
                                              int wm, int wn, Frags& F)
{
    const uint32_t Ab = base + st;
    const uint32_t Bb = base + st + 16384;
    const int m8 = lane >> 3, l7 = lane & 7;
    #pragma unroll
    for (int ks = 0; ks < 2; ks++) {
        uint32_t ah[2][4], al[2][4];
        #pragma unroll
        for (int mi = 0; mi < 2; mi++) {
            int rr = wm * 32 + mi * 16 + (m8 & 1) * 8 + l7;
            int ch = ks * 2 + (m8 >> 1);
            int p = ch ^ ((rr >> 1) & 3);
            uint32_t off = (uint32_t)(rr * 64 + p * 16);
            ldsm4(ah[mi], Ab + off);
            ldsm4(al[mi], Ab + 8192 + off);
        }
        #pragma unroll
        for (int jp = 0; jp < 4; jp++) {
            int nrow = wn * 64 + jp * 16 + (m8 >> 1) * 8 + l7;
            int ch = ks * 2 + (m8 & 1);
            int p = ch ^ ((nrow >> 1) & 3);
            uint32_t off = (uint32_t)(nrow * 64 + p * 16);
            uint32_t th[4], tl[4];
            ldsm4(th, Bb + off);
            ldsm4(tl, Bb + 8192 + off);
            #pragma unroll
            for (int mi = 0; mi < 2; mi++) {
                mma_bf16(F.acc[mi][2 * jp], ah[mi], th[0], th[1]);
                mma_bf16(F.acc[mi][2 * jp], ah[mi], tl[0], tl[1]);
                mma_bf16(F.acc[mi][2 * jp], al[mi], th[0], th[1]);
                mma_bf16(F.acc[mi][2 * jp + 1], ah[mi], th[2], th[3]);
                mma_bf16(F.acc[mi][2 * jp + 1], ah[mi], tl[2], tl[3]);
                mma_bf16(F.acc[mi][2 * jp + 1], al[mi], th[2], th[3]);
            }
        }
    }
}

// ---------------------------------------------------------------------------
// GEMM1: H = gelu(X @ W1 + b1).  A = X hi/lo [32768][768], B = W1t [3072][768]
// Grid (24, 256), 256 threads, 2 CTAs/SM.
// ---------------------------------------------------------------------------
__global__ void __launch_bounds__(256, 2)
k_mm1(const float* __restrict__ b1)
{
    extern __shared__ char smem[];
    const uint32_t base = smem_u32(smem);
    const int tid = threadIdx.x, wid = tid >> 5, lane = tid & 31;
    const int bx = blockIdx.x, by = blockIdx.y;
    const int K = 768, NC = 24;
    const int wm = wid & 3, wn = wid >> 2;

    auto issue = [&](int c) {
        int st = (c % NSTAGES) * STAGE_BYTES;
        #pragma unroll
        for (int t = 0; t < 8; t++) {
            int idx = tid + t * 256;
            int half = idx >> 9, w = idx & 511, r = w >> 2, ch = w & 3;
            int p = ch ^ ((r >> 1) & 3);
            uint32_t sa = base + st + half * 8192 + r * 64 + p * 16;
            const __nv_bfloat16* src;
            size_t grow;
            if (half < 2) { src = half ? g_Xlo : g_Xhi;  grow = (size_t)(by * 128 + r) * K; }
            else          { src = (half == 3) ? g_W1lo : g_W1hi; grow = (size_t)(bx * 128 + r) * K; }
            cp16(sa, src + grow + c * 32 + ch * 8);
        }
        CP_COMMIT();
    };

    Frags F;
    #pragma unroll
    for (int mi = 0; mi < 2; mi++)
        #pragma unroll
        for (int nj = 0; nj < 8; nj++)
            #pragma unroll
            for (int q = 0; q < 4; q++) F.acc[mi][nj][q] = 0.0f;

    issue(0);
    issue(1);
    for (int c = 0; c < NC; c++) {
        if (c + 2 < NC) { issue(c + 2); CP_WAIT(2); }
        else if (c + 1 < NC) { CP_WAIT(1); }
        else { CP_WAIT(0); }
        __syncthreads();
        compute_chunk(base, (c % NSTAGES) * STAGE_BYTES, lane, wm, wn, F);
        __syncthreads();
    }

    // epilogue: bias + exact GELU -> split hi/lo bf16 into H
    const int g = lane >> 2, t4 = lane & 3;
    #pragma unroll
    for (int mi = 0; mi < 2; mi++) {
        #pragma unroll
        for (int nj = 0; nj < 8; nj++) {
            int row0 = by * 128 + wm * 32 + mi * 16 + g;
            int col  = bx * 128 + wn * 64 + nj * 8 + 2 * t4;
            float2 bb = *(const float2*)(b1 + col);
            float x0 = gelu_exact(F.acc[mi][nj][0] + bb.x);
            float x1 = gelu_exact(F.acc[mi][nj][1] + bb.y);
            float x2 = gelu_exact(F.acc[mi][nj][2] + bb.x);
            float x3 = gelu_exact(F.acc[mi][nj][3] + bb.y);
            uint32_t h01 = pack_bf2(x0, x1), h23 = pack_bf2(x2, x3);
            __nv_bfloat162 hb01 = *reinterpret_cast<__nv_bfloat162*>(&h01);
            __nv_bfloat162 hb23 = *reinterpret_cast<__nv_bfloat162*>(&h23);
            uint32_t l01 = pack_bf2(x0 - __bfloat162float(__low2bfloat16(hb01)),
                                    x1 - __bfloat162float(__high2bfloat16(hb01)));
            uint32_t l23 = pack_bf2(x2 - __bfloat162float(__low2bfloat16(hb23)),
                                    x3 - __bfloat162float(__high2bfloat16(hb23)));
            *(uint32_t*)(g_Hhi + (size_t)row0 * 3072 + col) = h01;
            *(uint32_t*)(g_Hlo + (size_t)row0 * 3072 + col) = l01;
            *(uint32_t*)(g_Hhi + (size_t)(row0 + 8) * 3072 + col) = h23;
            *(uint32_t*)(g_Hlo + (size_t)(row0 + 8) * 3072 + col) = l23;
        }
    }
}

// ---------------------------------------------------------------------------
// GEMM2: out = H @ [W2 | We[idx]] + [b2 | be[idx]].  Grid (6, 256), 2 CTAs/SM.
// B rows n<576 from W2t, n>=576 from Wet[e]; 128-row M tiles never straddle
// a batch (1024 rows / batch).
// ---------------------------------------------------------------------------
__global__ void __launch_bounds__(256, 2)
k_mm2(const float* __restrict__ b2, const float* __restrict__ be,
      const int* __restrict__ idx32, float* __restrict__ out)
{
    extern __shared__ char smem[];
    const uint32_t base = smem_u32(smem);
    const int tid = threadIdx.x, wid = tid >> 5, lane = tid & 31;
    const int bx = blockIdx.x, by = blockIdx.y;
    const int K = 3072, NC = 96;
    const int wm = wid & 3, wn = wid >> 2;
    const int e = load_expert_index(idx32, by >> 3);

    auto issue = [&](int c) {
        int st = (c % NSTAGES) * STAGE_BYTES;
        #pragma unroll
        for (int t = 0; t < 8; t++) {
            int idx = tid + t * 256;
            int half = idx >> 9, w = idx & 511, r = w >> 2, ch = w & 3;
            int p = ch ^ ((r >> 1) & 3);
            uint32_t sa = base + st + half * 8192 + r * 64 + p * 16;
            const __nv_bfloat16* src;
            size_t grow;
            if (half < 2) {
                src = half ? g_Hlo : g_Hhi;
                grow = (size_t)(by * 128 + r) * K;
            } else {
                int n = bx * 128 + r;
                if (n < 576) { src = (half == 3) ? g_W2lo : g_W2hi; grow = (size_t)n * K; }
                else { src = (half == 3) ? g_Welo : g_Wehi;
                       grow = ((size_t)e * 192 + (n - 576)) * K; }
            }
            cp16(sa, src + grow + c * 32 + ch * 8);
        }
        CP_COMMIT();
    };

    Frags F;
    #pragma unroll
    for (int mi = 0; mi < 2; mi++)
        #pragma unroll
        for (int nj = 0; nj < 8; nj++)
            #pragma unroll
            for (int q = 0; q < 4; q++) F.acc[mi][nj][q] = 0.0f;

    issue(0);
    issue(1);
    for (int c = 0; c < NC; c++) {
        if (c + 2 < NC) { issue(c + 2); CP_WAIT(2); }
        else if (c + 1 < NC) { CP_WAIT(1); }
        else { CP_WAIT(0); }
        __syncthreads();
        compute_chunk(base, (c % NSTAGES) * STAGE_BYTES, lane, wm, wn, F);
        __syncthreads();
    }

    // epilogue: + bias (shared / expert), fp32 out [32768][768]
    const int g = lane >> 2, t4 = lane & 3;
    #pragma unroll
    for (int mi = 0; mi < 2; mi++) {
        #pragma unroll
        for (int nj = 0; nj < 8; nj++) {
            int row0 = by * 128 + wm * 32 + mi * 16 + g;
            int col  = bx * 128 + wn * 64 + nj * 8 + 2 * t4;
            float bx0, bx1;
            if (col < 576) { float2 bb = *(const float2*)(b2 + col); bx0 = bb.x; bx1 = bb.y; }
            else { float2 bb = *(const float2*)(be + e * 192 + (col - 576)); bx0 = bb.x; bx1 = bb.y; }
            float2 v0 = make_float2(F.acc[mi][nj][0] + bx0, F.acc[mi][nj][1] + bx1);
            float2 v1 = make_float2(F.acc[mi][nj][2] + bx0, F.acc[mi][nj][3] + bx1);
            *(float2*)(out + (size_t)row0 * 768 + col) = v0;
            *(float2*)(out + (size_t)(row0 + 8) * 768 + col) = v1;
        }
    }
}

// ---------------------------------------------------------------------------
extern "C" void kernel_launch(void* const* d_in, const int* in_sizes, int n_in,
                              void* d_out, int out_size)
{
    (void)in_sizes; (void)n_in; (void)out_size;
    const float* X   = (const float*)d_in[0];
    const int*   idx = (const int*)d_in[1];
    const float* W1  = (const float*)d_in[2];
    const float* b1  = (const float*)d_in[3];
    const float* W2  = (const float*)d_in[4];
    const float* b2  = (const float*)d_in[5];
    const float* We  = (const float*)d_in[6];
    const float* be  = (const float*)d_in[7];
    float* out = (float*)d_out;

    cudaFuncSetAttribute(k_mm1, cudaFuncAttributeMaxDynamicSharedMemorySize, SMEM_TOTAL);
    cudaFuncSetAttribute(k_mm2, cudaFuncAttributeMaxDynamicSharedMemorySize, SMEM_TOTAL);

    __nv_bfloat16 *xhi, *xlo, *w1hi, *w1lo, *w2hi, *w2lo, *wehi, *welo;
    cudaGetSymbolAddress((void**)&xhi,  g_Xhi);
    cudaGetSymbolAddress((void**)&xlo,  g_Xlo);
    cudaGetSymbolAddress((void**)&w1hi, g_W1hi);
    cudaGetSymbolAddress((void**)&w1lo, g_W1lo);
    cudaGetSymbolAddress((void**)&w2hi, g_W2hi);
    cudaGetSymbolAddress((void**)&w2lo, g_W2lo);
    cudaGetSymbolAddress((void**)&wehi, g_Wehi);
    cudaGetSymbolAddress((void**)&welo, g_Welo);

    {
        size_t n = (size_t)32768 * 768;
        k_split<<<(unsigned)(n / (256 * 4)), 256>>>(X, xhi, xlo, n);
    }
    {
        dim3 b(32, 8);
        k_tsplit<<<dim3(3072 / 32, 768 / 32, 1), b>>>(W1, w1hi, w1lo, 768, 3072);
        k_tsplit<<<dim3(576 / 32, 3072 / 32, 1), b>>>(W2, w2hi, w2lo, 3072, 576);
        k_tsplit<<<dim3(192 / 32, 3072 / 32, 6), b>>>(We, wehi, welo, 3072, 192);
    }

    k_mm1<<<dim3(3072 / 128, 32768 / 128), 256, SMEM_TOTAL>>>(b1);
    k_mm2<<<dim3(768 / 128, 32768 / 128), 256, SMEM_TOTAL>>>(b2, be, idx, out);
}

// round 8
// speedup vs baseline: 4.1185x; 1.4431x over previous
#include <cuda_runtime.h>
#include <cuda_fp16.h>
#include <stdint.h>

// ---------------------------------------------------------------------------
// fp16 2-product emulated-fp32 GEMMs on mma.sync (tcgen05 unavailable at
// virtual target compute_103). Weights split hi/lo fp16 (~22-bit), activations
// single fp16. CTA tile 128x128, Kc=32, 4-stage cp.async, one barrier/chunk,
// 2 CTAs/SM.
// ---------------------------------------------------------------------------

#define STAGE_BYTES 24576          // A 8K | Bhi 8K | Blo 8K
#define NSTAGES 4
#define SMEM_TOTAL (NSTAGES * STAGE_BYTES)   // 96 KB

// ---------------- static device scratch (no allocations allowed) -----------
static __device__ __align__(16) __half g_Xh [(size_t)32768 * 768];
static __device__ __align__(16) __half g_W1hi[(size_t)3072 * 768];    // [N][K]
static __device__ __align__(16) __half g_W1lo[(size_t)3072 * 768];
static __device__ __align__(16) __half g_W2hi[(size_t)576 * 3072];    // [N][K]
static __device__ __align__(16) __half g_W2lo[(size_t)576 * 3072];
static __device__ __align__(16) __half g_Wehi[(size_t)6 * 192 * 3072];
static __device__ __align__(16) __half g_Welo[(size_t)6 * 192 * 3072];
static __device__ __align__(16) __half g_Hf [(size_t)32768 * 3072];

// ---------------- PTX helpers ----------------------------------------------
__device__ __forceinline__ uint32_t smem_u32(const void* p) {
    uint32_t a;
    asm("{ .reg .u64 t; cvta.to.shared.u64 t, %1; cvt.u32.u64 %0, t; }" : "=r"(a) : "l"(p));
    return a;
}
__device__ __forceinline__ void cp16(uint32_t saddr, const void* g) {
    asm volatile("cp.async.cg.shared.global [%0], [%1], 16;" :: "r"(saddr), "l"(g));
}
#define CP_COMMIT() asm volatile("cp.async.commit_group;" ::: "memory")
#define CP_WAIT(n)  asm volatile("cp.async.wait_group " #n ";" ::: "memory")

__device__ __forceinline__ void ldsm4(uint32_t* r, uint32_t addr) {
    asm volatile("ldmatrix.sync.aligned.m8n8.x4.shared.b16 {%0,%1,%2,%3}, [%4];"
        : "=r"(r[0]), "=r"(r[1]), "=r"(r[2]), "=r"(r[3]) : "r"(addr));
}
__device__ __forceinline__ void mma_f16(float* c, const uint32_t* a,
                                        uint32_t b0, uint32_t b1) {
    asm volatile("mma.sync.aligned.m16n8k16.row.col.f32.f16.f16.f32 "
        "{%0,%1,%2,%3}, {%4,%5,%6,%7}, {%8,%9}, {%0,%1,%2,%3};"
        : "+f"(c[0]), "+f"(c[1]), "+f"(c[2]), "+f"(c[3])
        : "r"(a[0]), "r"(a[1]), "r"(a[2]), "r"(a[3]), "r"(b0), "r"(b1));
}

__device__ __forceinline__ float gelu_exact(float x) {
    return 0.5f * x * (1.0f + erff(x * 0.7071067811865475244f));
}
// int64-vs-int32 robust expert index (values in [0,6) -> int64 odd words all 0)
__device__ __forceinline__ int load_expert_index(const int* __restrict__ idx32, int b) {
    int odd_or = 0;
    #pragma unroll
    for (int j = 1; j < 32; j += 2) odd_or |= idx32[j];
    return (odd_or == 0) ? idx32[2 * b] : idx32[b];
}

// ---------------- prep kernels ----------------------------------------------
// fp32 -> fp16 elementwise (vectorized x4)
__global__ void k_half(const float* __restrict__ s, __half* __restrict__ d, size_t n)
{
    size_t i = ((size_t)blockIdx.x * blockDim.x + threadIdx.x) * 4;
    if (i >= n) return;
    float4 v = *(const float4*)(s + i);
    __half2 a = __floats2half2_rn(v.x, v.y);
    __half2 b = __floats2half2_rn(v.z, v.w);
    uint2 o;
    o.x = *reinterpret_cast<uint32_t*>(&a);
    o.y = *reinterpret_cast<uint32_t*>(&b);
    *(uint2*)(d + i) = o;
}

// transpose [R][C] fp32 -> [C][R] fp16 hi/lo (batched over z)
__global__ void k_tsplit_h(const float* __restrict__ src, __half* __restrict__ dhi,
                           __half* __restrict__ dlo, int R, int C)
{
    __shared__ float t[32][33];
    size_t zo = (size_t)blockIdx.z * R * C;
    int bx = blockIdx.x * 32, by = blockIdx.y * 32;
    int tx = threadIdx.x, ty = threadIdx.y;  // (32, 8)
    #pragma unroll
    for (int i = 0; i < 32; i += 8)
        t[ty + i][tx] = src[zo + (size_t)(by + ty + i) * C + bx + tx];
    __syncthreads();
    #pragma unroll
    for (int i = 0; i < 32; i += 8) {
        float v = t[tx][ty + i];
        __half h = __float2half_rn(v);
        float l = v - __half2float(h);
        size_t o = zo + (size_t)(bx + ty + i) * R + (by + tx);
        dhi[o] = h;
        dlo[o] = __float2half_rn(l);
    }
}

// ---------------------------------------------------------------------------
// Mainloop compute: per chunk c, stage st = (c % 4) * 24576;
// A at +0, Bhi +8192, Blo +16384. SMEM row = 64 B (32 fp16);
// 16B chunk swizzle p = ch ^ ((r>>1)&3).
// Per k16-step: A frags single; B hi/lo per jp consumed immediately.
// ---------------------------------------------------------------------------

struct Frags {
    float acc[2][8][4];
};

__device__ __forceinline__ void compute_chunk(uint32_t base, int st, int lane,
                                              int wm, int wn, Frags& F)
{
    const uint32_t Ab = base + st;
    const uint32_t Bh = base + st + 8192;
    const uint32_t Bl = base + st + 16384;
    const int m8 = lane >> 3, l7 = lane & 7;
    #pragma unroll
    for (int ks = 0; ks < 2; ks++) {
        uint32_t a[2][4];
        #pragma unroll
        for (int mi = 0; mi < 2; mi++) {
            int rr = wm * 32 + mi * 16 + (m8 & 1) * 8 + l7;
            int ch = ks * 2 + (m8 >> 1);
            int p = ch ^ ((rr >> 1) & 3);
            ldsm4(a[mi], Ab + (uint32_t)(rr * 64 + p * 16));
        }
        #pragma unroll
        for (int jp = 0; jp < 4; jp++) {
            int nrow = wn * 64 + jp * 16 + (m8 >> 1) * 8 + l7;
            int ch = ks * 2 + (m8 & 1);
            int p = ch ^ ((nrow >> 1) & 3);
            uint32_t off = (uint32_t)(nrow * 64 + p * 16);
            uint32_t th[4], tl[4];
            ldsm4(th, Bh + off);
            ldsm4(tl, Bl + off);
            #pragma unroll
            for (int mi = 0; mi < 2; mi++) {
                mma_f16(F.acc[mi][2 * jp],     a[mi], th[0], th[1]);
                mma_f16(F.acc[mi][2 * jp],     a[mi], tl[0], tl[1]);
                mma_f16(F.acc[mi][2 * jp + 1], a[mi], th[2], th[3]);
                mma_f16(F.acc[mi][2 * jp + 1], a[mi], tl[2], tl[3]);
            }
        }
    }
}

// ---------------------------------------------------------------------------
// GEMM1: H = gelu(X @ W1 + b1).  A = Xh [32768][768], B = W1t hi/lo [3072][768]
// Grid (24, 256), 256 threads, 2 CTAs/SM.
// ---------------------------------------------------------------------------
__global__ void __launch_bounds__(256, 2)
k_mm1(const float* __restrict__ b1)
{
    extern __shared__ char smem[];
    const uint32_t base = smem_u32(smem);
    const int tid = threadIdx.x, wid = tid >> 5, lane = tid & 31;
    const int bx = blockIdx.x, by = blockIdx.y;
    const int K = 768, NC = 24;
    const int wm = wid & 3, wn = wid >> 2;

    auto issue = [&](int c) {
        int st = (c % NSTAGES) * STAGE_BYTES;
        #pragma unroll
        for (int t = 0; t < 6; t++) {
            int idx = tid + t * 256;
            int third = idx >> 9, w = idx & 511, r = w >> 2, ch = w & 3;
            int p = ch ^ ((r >> 1) & 3);
            uint32_t sa = base + st + third * 8192 + r * 64 + p * 16;
            const __half* src;
            size_t grow;
            if (third == 0)      { src = g_Xh;   grow = (size_t)(by * 128 + r) * K; }
            else if (third == 1) { src = g_W1hi; grow = (size_t)(bx * 128 + r) * K; }
            else                 { src = g_W1lo; grow = (size_t)(bx * 128 + r) * K; }
            cp16(sa, src + grow + c * 32 + ch * 8);
        }
        CP_COMMIT();
    };

    Frags F;
    #pragma unroll
    for (int mi = 0; mi < 2; mi++)
        #pragma unroll
        for (int nj = 0; nj < 8; nj++)
            #pragma unroll
            for (int q = 0; q < 4; q++) F.acc[mi][nj][q] = 0.0f;

    issue(0);
    issue(1);
    issue(2);
    for (int c = 0; c < NC; c++) {
        CP_WAIT(2);
        __syncthreads();
        if (c + 3 < NC) issue(c + 3); else CP_COMMIT();
        compute_chunk(base, (c % NSTAGES) * STAGE_BYTES, lane, wm, wn, F);
    }

    // epilogue: bias + exact GELU -> fp16 into H
    const int g = lane >> 2, t4 = lane & 3;
    #pragma unroll
    for (int mi = 0; mi < 2; mi++) {
        #pragma unroll
        for (int nj = 0; nj < 8; nj++) {
            int row0 = by * 128 + wm * 32 + mi * 16 + g;
            int col  = bx * 128 + wn * 64 + nj * 8 + 2 * t4;
            float2 bb = *(const float2*)(b1 + col);
            float x0 = gelu_exact(F.acc[mi][nj][0] + bb.x);
            float x1 = gelu_exact(F.acc[mi][nj][1] + bb.y);
            float x2 = gelu_exact(F.acc[mi][nj][2] + bb.x);
            float x3 = gelu_exact(F.acc[mi][nj][3] + bb.y);
            __half2 h01 = __floats2half2_rn(x0, x1);
            __half2 h23 = __floats2half2_rn(x2, x3);
            *(uint32_t*)(g_Hf + (size_t)row0 * 3072 + col) =
                *reinterpret_cast<uint32_t*>(&h01);
            *(uint32_t*)(g_Hf + (size_t)(row0 + 8) * 3072 + col) =
                *reinterpret_cast<uint32_t*>(&h23);
        }
    }
}

// ---------------------------------------------------------------------------
// GEMM2: out = H @ [W2 | We[idx]] + [b2 | be[idx]].  Grid (6, 256), 2 CTAs/SM.
// B rows n<576 from W2t hi/lo, n>=576 from Wet[e] hi/lo; 128-row M tiles
// never straddle a batch (1024 rows / batch).
// ---------------------------------------------------------------------------
__global__ void __launch_bounds__(256, 2)
k_mm2(const float* __restrict__ b2, const float* __restrict__ be,
      const int* __restrict__ idx32, float* __restrict__ out)
{
    extern __shared__ char smem[];
    const uint32_t base = smem_u32(smem);
    const int tid = threadIdx.x, wid = tid >> 5, lane = tid & 31;
    const int bx = blockIdx.x, by = blockIdx.y;
    const int K = 3072, NC = 96;
    const int wm = wid & 3, wn = wid >> 2;
    const int e = load_expert_index(idx32, by >> 3);

    auto issue = [&](int c) {
        int st = (c % NSTAGES) * STAGE_BYTES;
        #pragma unroll
        for (int t = 0; t < 6; t++) {
            int idx = tid + t * 256;
            int third = idx >> 9, w = idx & 511, r = w >> 2, ch = w & 3;
            int p = ch ^ ((r >> 1) & 3);
            uint32_t sa = base + st + third * 8192 + r * 64 + p * 16;
            const __half* src;
            size_t grow;
            if (third == 0) {
                src = g_Hf;
                grow = (size_t)(by * 128 + r) * K;
            } else {
                int n = bx * 128 + r;
                if (n < 576) {
                    src = (third == 2) ? g_W2lo : g_W2hi;
                    grow = (size_t)n * K;
                } else {
                    src = (third == 2) ? g_Welo : g_Wehi;
                    grow = ((size_t)e * 192 + (n - 576)) * K;
                }
            }
            cp16(sa, src + grow + c * 32 + ch * 8);
        }
        CP_COMMIT();
    };

    Frags F;
    #pragma unroll
    for (int mi = 0; mi < 2; mi++)
        #pragma unroll
        for (int nj = 0; nj < 8; nj++)
            #pragma unroll
            for (int q = 0; q < 4; q++) F.acc[mi][nj][q] = 0.0f;

    issue(0);
    issue(1);
    issue(2);
    for (int c = 0; c < NC; c++) {
        CP_WAIT(2);
        __syncthreads();
        if (c + 3 < NC) issue(c + 3); else CP_COMMIT();
        compute_chunk(base, (c % NSTAGES) * STAGE_BYTES, lane, wm, wn, F);
    }

    // epilogue: + bias (shared / expert), fp32 out [32768][768]
    const int g = lane >> 2, t4 = lane & 3;
    #pragma unroll
    for (int mi = 0; mi < 2; mi++) {
        #pragma unroll
        for (int nj = 0; nj < 8; nj++) {
            int row0 = by * 128 + wm * 32 + mi * 16 + g;
            int col  = bx * 128 + wn * 64 + nj * 8 + 2 * t4;
            float bx0, bx1;
            if (col < 576) { float2 bb = *(const float2*)(b2 + col); bx0 = bb.x; bx1 = bb.y; }
            else { float2 bb = *(const float2*)(be + e * 192 + (col - 576)); bx0 = bb.x; bx1 = bb.y; }
            float2 v0 = make_float2(F.acc[mi][nj][0] + bx0, F.acc[mi][nj][1] + bx1);
            float2 v1 = make_float2(F.acc[mi][nj][2] + bx0, F.acc[mi][nj][3] + bx1);
            *(float2*)(out + (size_t)row0 * 768 + col) = v0;
            *(float2*)(out + (size_t)(row0 + 8) * 768 + col) = v1;
        }
    }
}

// ---------------------------------------------------------------------------
extern "C" void kernel_launch(void* const* d_in, const int* in_sizes, int n_in,
                              void* d_out, int out_size)
{
    (void)in_sizes; (void)n_in; (void)out_size;
    const float* X   = (const float*)d_in[0];
    const int*   idx = (const int*)d_in[1];
    const float* W1  = (const float*)d_in[2];
    const float* b1  = (const float*)d_in[3];
    const float* W2  = (const float*)d_in[4];
    const float* b2  = (const float*)d_in[5];
    const float* We  = (const float*)d_in[6];
    const float* be  = (const float*)d_in[7];
    float* out = (float*)d_out;

    cudaFuncSetAttribute(k_mm1, cudaFuncAttributeMaxDynamicSharedMemorySize, SMEM_TOTAL);
    cudaFuncSetAttribute(k_mm2, cudaFuncAttributeMaxDynamicSharedMemorySize, SMEM_TOTAL);

    __half *xh, *w1hi, *w1lo, *w2hi, *w2lo, *wehi, *welo;
    cudaGetSymbolAddress((void**)&xh,   g_Xh);
    cudaGetSymbolAddress((void**)&w1hi, g_W1hi);
    cudaGetSymbolAddress((void**)&w1lo, g_W1lo);
    cudaGetSymbolAddress((void**)&w2hi, g_W2hi);
    cudaGetSymbolAddress((void**)&w2lo, g_W2lo);
    cudaGetSymbolAddress((void**)&wehi, g_Wehi);
    cudaGetSymbolAddress((void**)&welo, g_Welo);

    {
        size_t n = (size_t)32768 * 768;
        k_half<<<(unsigned)(n / (256 * 4)), 256>>>(X, xh, n);
    }
    {
        dim3 b(32, 8);
        k_tsplit_h<<<dim3(3072 / 32, 768 / 32, 1), b>>>(W1, w1hi, w1lo, 768, 3072);
        k_tsplit_h<<<dim3(576 / 32, 3072 / 32, 1), b>>>(W2, w2hi, w2lo, 3072, 576);
        k_tsplit_h<<<dim3(192 / 32, 3072 / 32, 6), b>>>(We, wehi, welo, 3072, 192);
    }

    k_mm1<<<dim3(3072 / 128, 32768 / 128), 256, SMEM_TOTAL>>>(b1);
    k_mm2<<<dim3(768 / 128, 32768 / 128), 256, SMEM_TOTAL>>>(b2, be, idx, out);
}

// round 9
// speedup vs baseline: 6.8183x; 1.6555x over previous
#include <cuda_runtime.h>
#include <cuda_fp16.h>
#include <stdint.h>

// ---------------------------------------------------------------------------
// Pure fp16 GEMMs (fp32 accum) on mma.sync. Validated quadrature error model:
// 5 quant sources x ~1.7e-4 => ~3.8e-4 total, under the 1e-3 threshold.
// CTA tile 128x128, Kc=32, 6-stage cp.async pipeline (5-deep prefetch),
// one barrier per chunk, 2 CTAs/SM.
// ---------------------------------------------------------------------------

#define STAGE_BYTES 16384          // A 8K | B 8K
#define NSTAGES 6
#define SMEM_TOTAL (NSTAGES * STAGE_BYTES)   // 96 KB

// ---------------- static device scratch (no allocations allowed) -----------
static __device__ __align__(16) __half g_Xh [(size_t)32768 * 768];
static __device__ __align__(16) __half g_W1t[(size_t)3072 * 768];     // [N][K]
static __device__ __align__(16) __half g_W2t[(size_t)576 * 3072];     // [N][K]
static __device__ __align__(16) __half g_Wet[(size_t)6 * 192 * 3072];
static __device__ __align__(16) __half g_Hf [(size_t)32768 * 3072];

// ---------------- PTX helpers ----------------------------------------------
__device__ __forceinline__ uint32_t smem_u32(const void* p) {
    uint32_t a;
    asm("{ .reg .u64 t; cvta.to.shared.u64 t, %1; cvt.u32.u64 %0, t; }" : "=r"(a) : "l"(p));
    return a;
}
__device__ __forceinline__ void cp16(uint32_t saddr, const void* g) {
    asm volatile("cp.async.cg.shared.global [%0], [%1], 16;" :: "r"(saddr), "l"(g));
}
#define CP_COMMIT() asm volatile("cp.async.commit_group;" ::: "memory")
#define CP_WAIT(n)  asm volatile("cp.async.wait_group " #n ";" ::: "memory")

__device__ __forceinline__ void ldsm4(uint32_t* r, uint32_t addr) {
    asm volatile("ldmatrix.sync.aligned.m8n8.x4.shared.b16 {%0,%1,%2,%3}, [%4];"
        : "=r"(r[0]), "=r"(r[1]), "=r"(r[2]), "=r"(r[3]) : "r"(addr));
}
__device__ __forceinline__ void mma_f16(float* c, const uint32_t* a,
                                        uint32_t b0, uint32_t b1) {
    asm volatile("mma.sync.aligned.m16n8k16.row.col.f32.f16.f16.f32 "
        "{%0,%1,%2,%3}, {%4,%5,%6,%7}, {%8,%9}, {%0,%1,%2,%3};"
        : "+f"(c[0]), "+f"(c[1]), "+f"(c[2]), "+f"(c[3])
        : "r"(a[0]), "r"(a[1]), "r"(a[2]), "r"(a[3]), "r"(b0), "r"(b1));
}

__device__ __forceinline__ float gelu_exact(float x) {
    return 0.5f * x * (1.0f + erff(x * 0.7071067811865475244f));
}
// int64-vs-int32 robust expert index (values in [0,6) -> int64 odd words all 0)
__device__ __forceinline__ int load_expert_index(const int* __restrict__ idx32, int b) {
    int odd_or = 0;
    #pragma unroll
    for (int j = 1; j < 32; j += 2) odd_or |= idx32[j];
    return (odd_or == 0) ? idx32[2 * b] : idx32[b];
}

// ---------------- prep kernels ----------------------------------------------
// fp32 -> fp16 elementwise (vectorized x4)
__global__ void k_half(const float* __restrict__ s, __half* __restrict__ d, size_t n)
{
    size_t i = ((size_t)blockIdx.x * blockDim.x + threadIdx.x) * 4;
    if (i >= n) return;
    float4 v = *(const float4*)(s + i);
    __half2 a = __floats2half2_rn(v.x, v.y);
    __half2 b = __floats2half2_rn(v.z, v.w);
    uint2 o;
    o.x = *reinterpret_cast<uint32_t*>(&a);
    o.y = *reinterpret_cast<uint32_t*>(&b);
    *(uint2*)(d + i) = o;
}

// transpose [R][C] fp32 -> [C][R] fp16 (batched over z)
__global__ void k_thalf(const float* __restrict__ src, __half* __restrict__ dst,
                        int R, int C)
{
    __shared__ float t[32][33];
    size_t zo = (size_t)blockIdx.z * R * C;
    int bx = blockIdx.x * 32, by = blockIdx.y * 32;
    int tx = threadIdx.x, ty = threadIdx.y;  // (32, 8)
    #pragma unroll
    for (int i = 0; i < 32; i += 8)
        t[ty + i][tx] = src[zo + (size_t)(by + ty + i) * C + bx + tx];
    __syncthreads();
    #pragma unroll
    for (int i = 0; i < 32; i += 8) {
        size_t o = zo + (size_t)(bx + ty + i) * R + (by + tx);
        dst[o] = __float2half_rn(t[tx][ty + i]);
    }
}

// ---------------------------------------------------------------------------
// Mainloop compute: per chunk c, stage st = (c % 6) * 16384;
// A at +0, B at +8192. SMEM row = 64 B (32 fp16);
// 16B chunk swizzle p = ch ^ ((r>>1)&3).
// ---------------------------------------------------------------------------

struct Frags {
    float acc[2][8][4];
};

__device__ __forceinline__ void compute_chunk(uint32_t base, int st, int lane,
                                              int wm, int wn, Frags& F)
{
    const uint32_t Ab = base + st;
    const uint32_t Bb = base + st + 8192;
    const int m8 = lane >> 3, l7 = lane & 7;
    #pragma unroll
    for (int ks = 0; ks < 2; ks++) {
        uint32_t a[2][4];
        #pragma unroll
        for (int mi = 0; mi < 2; mi++) {
            int rr = wm * 32 + mi * 16 + (m8 & 1) * 8 + l7;
            int ch = ks * 2 + (m8 >> 1);
            int p = ch ^ ((rr >> 1) & 3);
            ldsm4(a[mi], Ab + (uint32_t)(rr * 64 + p * 16));
        }
        #pragma unroll
        for (int jp = 0; jp < 4; jp++) {
            int nrow = wn * 64 + jp * 16 + (m8 >> 1) * 8 + l7;
            int ch = ks * 2 + (m8 & 1);
            int p = ch ^ ((nrow >> 1) & 3);
            uint32_t tb[4];
            ldsm4(tb, Bb + (uint32_t)(nrow * 64 + p * 16));
            #pragma unroll
            for (int mi = 0; mi < 2; mi++) {
                mma_f16(F.acc[mi][2 * jp],     a[mi], tb[0], tb[1]);
                mma_f16(F.acc[mi][2 * jp + 1], a[mi], tb[2], tb[3]);
            }
        }
    }
}

// ---------------------------------------------------------------------------
// GEMM1: H = gelu(X @ W1 + b1).  A = Xh [32768][768], B = W1t [3072][768]
// Grid (24, 256), 256 threads, 2 CTAs/SM.
// ---------------------------------------------------------------------------
__global__ void __launch_bounds__(256, 2)
k_mm1(const float* __restrict__ b1)
{
    extern __shared__ char smem[];
    const uint32_t base = smem_u32(smem);
    const int tid = threadIdx.x, wid = tid >> 5, lane = tid & 31;
    const int bx = blockIdx.x, by = blockIdx.y;
    const int K = 768, NC = 24;
    const int wm = wid & 3, wn = wid >> 2;

    auto issue = [&](int c) {
        int st = (c % NSTAGES) * STAGE_BYTES;
        #pragma unroll
        for (int t = 0; t < 4; t++) {
            int idx = tid + t * 256;
            int half = idx >> 9, w = idx & 511, r = w >> 2, ch = w & 3;
            int p = ch ^ ((r >> 1) & 3);
            uint32_t sa = base + st + half * 8192 + r * 64 + p * 16;
            const __half* src;
            size_t grow;
            if (half == 0) { src = g_Xh;  grow = (size_t)(by * 128 + r) * K; }
            else           { src = g_W1t; grow = (size_t)(bx * 128 + r) * K; }
            cp16(sa, src + grow + c * 32 + ch * 8);
        }
        CP_COMMIT();
    };

    Frags F;
    #pragma unroll
    for (int mi = 0; mi < 2; mi++)
        #pragma unroll
        for (int nj = 0; nj < 8; nj++)
            #pragma unroll
            for (int q = 0; q < 4; q++) F.acc[mi][nj][q] = 0.0f;

    issue(0); issue(1); issue(2); issue(3); issue(4);
    for (int c = 0; c < NC; c++) {
        CP_WAIT(4);
        __syncthreads();
        if (c + 5 < NC) issue(c + 5); else CP_COMMIT();
        compute_chunk(base, (c % NSTAGES) * STAGE_BYTES, lane, wm, wn, F);
    }

    // epilogue: bias + exact GELU -> fp16 into H
    const int g = lane >> 2, t4 = lane & 3;
    #pragma unroll
    for (int mi = 0; mi < 2; mi++) {
        #pragma unroll
        for (int nj = 0; nj < 8; nj++) {
            int row0 = by * 128 + wm * 32 + mi * 16 + g;
            int col  = bx * 128 + wn * 64 + nj * 8 + 2 * t4;
            float2 bb = *(const float2*)(b1 + col);
            float x0 = gelu_exact(F.acc[mi][nj][0] + bb.x);
            float x1 = gelu_exact(F.acc[mi][nj][1] + bb.y);
            float x2 = gelu_exact(F.acc[mi][nj][2] + bb.x);
            float x3 = gelu_exact(F.acc[mi][nj][3] + bb.y);
            __half2 h01 = __floats2half2_rn(x0, x1);
            __half2 h23 = __floats2half2_rn(x2, x3);
            *(uint32_t*)(g_Hf + (size_t)row0 * 3072 + col) =
                *reinterpret_cast<uint32_t*>(&h01);
            *(uint32_t*)(g_Hf + (size_t)(row0 + 8) * 3072 + col) =
                *reinterpret_cast<uint32_t*>(&h23);
        }
    }
}

// ---------------------------------------------------------------------------
// GEMM2: out = H @ [W2 | We[idx]] + [b2 | be[idx]].  Grid (6, 256), 2 CTAs/SM.
// B rows n<576 from W2t, n>=576 from Wet[e]; 128-row M tiles never straddle
// a batch (1024 rows / batch).
// ---------------------------------------------------------------------------
__global__ void __launch_bounds__(256, 2)
k_mm2(const float* __restrict__ b2, const float* __restrict__ be,
      const int* __restrict__ idx32, float* __restrict__ out)
{
    extern __shared__ char smem[];
    const uint32_t base = smem_u32(smem);
    const int tid = threadIdx.x, wid = tid >> 5, lane = tid & 31;
    const int bx = blockIdx.x, by = blockIdx.y;
    const int K = 3072, NC = 96;
    const int wm = wid & 3, wn = wid >> 2;
    const int e = load_expert_index(idx32, by >> 3);

    auto issue = [&](int c) {
        int st = (c % NSTAGES) * STAGE_BYTES;
        #pragma unroll
        for (int t = 0; t < 4; t++) {
            int idx = tid + t * 256;
            int half = idx >> 9, w = idx & 511, r = w >> 2, ch = w & 3;
            int p = ch ^ ((r >> 1) & 3);
            uint32_t sa = base + st + half * 8192 + r * 64 + p * 16;
            const __half* src;
            size_t grow;
            if (half == 0) {
                src = g_Hf;
                grow = (size_t)(by * 128 + r) * K;
            } else {
                int n = bx * 128 + r;
                if (n < 576) { src = g_W2t; grow = (size_t)n * K; }
                else { src = g_Wet; grow = ((size_t)e * 192 + (n - 576)) * K; }
            }
            cp16(sa, src + grow + c * 32 + ch * 8);
        }
        CP_COMMIT();
    };

    Frags F;
    #pragma unroll
    for (int mi = 0; mi < 2; mi++)
        #pragma unroll
        for (int nj = 0; nj < 8; nj++)
            #pragma unroll
            for (int q = 0; q < 4; q++) F.acc[mi][nj][q] = 0.0f;

    issue(0); issue(1); issue(2); issue(3); issue(4);
    for (int c = 0; c < NC; c++) {
        CP_WAIT(4);
        __syncthreads();
        if (c + 5 < NC) issue(c + 5); else CP_COMMIT();
        compute_chunk(base, (c % NSTAGES) * STAGE_BYTES, lane, wm, wn, F);
    }

    // epilogue: + bias (shared / expert), fp32 out [32768][768]
    const int g = lane >> 2, t4 = lane & 3;
    #pragma unroll
    for (int mi = 0; mi < 2; mi++) {
        #pragma unroll
        for (int nj = 0; nj < 8; nj++) {
            int row0 = by * 128 + wm * 32 + mi * 16 + g;
            int col  = bx * 128 + wn * 64 + nj * 8 + 2 * t4;
            float bx0, bx1;
            if (col < 576) { float2 bb = *(const float2*)(b2 + col); bx0 = bb.x; bx1 = bb.y; }
            else { float2 bb = *(const float2*)(be + e * 192 + (col - 576)); bx0 = bb.x; bx1 = bb.y; }
            float2 v0 = make_float2(F.acc[mi][nj][0] + bx0, F.acc[mi][nj][1] + bx1);
            float2 v1 = make_float2(F.acc[mi][nj][2] + bx0, F.acc[mi][nj][3] + bx1);
            *(float2*)(out + (size_t)row0 * 768 + col) = v0;
            *(float2*)(out + (size_t)(row0 + 8) * 768 + col) = v1;
        }
    }
}

// ---------------------------------------------------------------------------
extern "C" void kernel_launch(void* const* d_in, const int* in_sizes, int n_in,
                              void* d_out, int out_size)
{
    (void)in_sizes; (void)n_in; (void)out_size;
    const float* X   = (const float*)d_in[0];
    const int*   idx = (const int*)d_in[1];
    const float* W1  = (const float*)d_in[2];
    const float* b1  = (const float*)d_in[3];
    const float* W2  = (const float*)d_in[4];
    const float* b2  = (const float*)d_in[5];
    const float* We  = (const float*)d_in[6];
    const float* be  = (const float*)d_in[7];
    float* out = (float*)d_out;

    cudaFuncSetAttribute(k_mm1, cudaFuncAttributeMaxDynamicSharedMemorySize, SMEM_TOTAL);
    cudaFuncSetAttribute(k_mm2, cudaFuncAttributeMaxDynamicSharedMemorySize, SMEM_TOTAL);

    __half *xh, *w1t, *w2t, *wet;
    cudaGetSymbolAddress((void**)&xh,  g_Xh);
    cudaGetSymbolAddress((void**)&w1t, g_W1t);
    cudaGetSymbolAddress((void**)&w2t, g_W2t);
    cudaGetSymbolAddress((void**)&wet, g_Wet);

    {
        size_t n = (size_t)32768 * 768;
        k_half<<<(unsigned)(n / (256 * 4)), 256>>>(X, xh, n);
    }
    {
        dim3 b(32, 8);
        k_thalf<<<dim3(3072 / 32, 768 / 32, 1), b>>>(W1, w1t, 768, 3072);
        k_thalf<<<dim3(576 / 32, 3072 / 32, 1), b>>>(W2, w2t, 3072, 576);
        k_thalf<<<dim3(192 / 32, 3072 / 32, 6), b>>>(We, wet, 3072, 192);
    }

    k_mm1<<<dim3(3072 / 128, 32768 / 128), 256, SMEM_TOTAL>>>(b1);
    k_mm2<<<dim3(768 / 128, 32768 / 128), 256, SMEM_TOTAL>>>(b2, be, idx, out);
}